// round 15
// baseline (speedup 1.0000x reference)
#include <cuda_runtime.h>
#include <cuda_bf16.h>
#include <cstdint>
#include <math.h>

#define B 32
#define S 64
#define T 64
#define E 512
#define H 512
#define V 32000
#define G3 1536
#define NB 250          // V / 128 partial tiles

#define ENC_BLOCKS 128
#define DEC_BLOCKS 128

__device__ float g_esrc[B * S * E];
__device__ float g_etgt[B * T * E];
__device__ float g_gxf[B * S * G3];
__device__ float g_gxb[B * S * G3];
__device__ float g_gxemb[B * T * G3];
__device__ float g_srchid[B * S * 2 * H];
__device__ float g_Uh[B * S * H];
__device__ float g_P[(size_t)B * G3 * S];
__device__ float g_hTf[2][H * B];
__device__ float g_hTb[2][H * B];
__device__ float g_hTd[2][H * B];
__device__ float g_Ah[B * H];
__device__ float g_alpha[B * S];
__device__ float g_pm[B * T * NB];
__device__ float g_ps[B * T * NB];
__device__ float g_rowres[B * T];
__device__ float g_zb[G3];
__device__ __nv_bfloat16 g_wbf[(size_t)V * H];
__device__ __nv_bfloat16 g_abf[B * T * H];
__device__ unsigned g_cnt_enc[32];
__device__ unsigned g_cnt_dec[32];

__device__ __forceinline__ float sigm(float x) { return 1.0f / (1.0f + expf(-x)); }
__device__ __forceinline__ float tanh_fast(float x) {
    float y; asm("tanh.approx.f32 %0, %1;" : "=f"(y) : "f"(x)); return y;
}
__device__ __forceinline__ void bar_sync(unsigned* cnt, unsigned target) {
    __syncthreads();
    if (threadIdx.x == 0) {
        asm volatile("fence.acq_rel.gpu;" ::: "memory");
        asm volatile("red.relaxed.gpu.add.u32 [%0], 1;" :: "l"(cnt) : "memory");
        unsigned v;
        do {
            asm volatile("ld.relaxed.gpu.u32 %0, [%1];" : "=r"(v) : "l"(cnt) : "memory");
        } while (v < target);
        asm volatile("fence.acq_rel.gpu;" ::: "memory");
    }
    __syncthreads();
}

__global__ void zero_h_kernel() {
    int idx = blockIdx.x * blockDim.x + threadIdx.x;
    if (idx < H * B) { g_hTf[0][idx] = 0.f; g_hTb[0][idx] = 0.f; g_hTd[0][idx] = 0.f; }
    if (idx < G3) g_zb[idx] = 0.f;
    if (idx == 0) { g_cnt_enc[0] = 0; g_cnt_dec[0] = 0; }
}

__global__ __launch_bounds__(128) void embed_kernel(
    const int* __restrict__ src_seqs, const int* __restrict__ tgt_seqs,
    const float* __restrict__ src_emb, const float* __restrict__ tgt_emb)
{
    int blk = blockIdx.x, tid = threadIdx.x;
    if (blk < B * S) {
        int tok = src_seqs[blk];
        ((float4*)(g_esrc + (size_t)blk * E))[tid] = ((const float4*)(src_emb + (size_t)tok * E))[tid];
    } else {
        int r = blk - B * S;
        int tok = tgt_seqs[r];
        ((float4*)(g_etgt + (size_t)r * E))[tid] = ((const float4*)(tgt_emb + (size_t)tok * E))[tid];
    }
}

// ---- fp32 GEMM: C=A@W^T+bias; TR=0 row-major, TR=1 [s][n][b], TR=2 [b][n][s] ----
#define GBM 128
#define GBN 64
#define GBK 16
template<int TR>
__global__ __launch_bounds__(256) void gemm_nt(
    const float* __restrict__ A, int lda,
    const float* __restrict__ W, int ldw,
    const float* __restrict__ bias,
    float* __restrict__ C, int ldc, int K, int sdim)
{
    __shared__ float As[GBK][GBM];
    __shared__ float Bs[GBK][GBN];
    int tid = threadIdx.x;
    int m0 = blockIdx.y * GBM, n0 = blockIdx.x * GBN;
    int tx = tid & 15, ty = tid >> 4;
    float acc[8][4];
#pragma unroll
    for (int i = 0; i < 8; i++)
#pragma unroll
        for (int j = 0; j < 4; j++) acc[i][j] = 0.f;
    int ar0 = tid >> 2, ak0 = (tid & 3) * 4;
    for (int k0 = 0; k0 < K; k0 += GBK) {
#pragma unroll
        for (int h = 0; h < 2; h++) {
            int r = ar0 + h * 64;
            float4 v = *(const float4*)(A + (size_t)(m0 + r) * lda + k0 + ak0);
            As[ak0 + 0][r] = v.x; As[ak0 + 1][r] = v.y; As[ak0 + 2][r] = v.z; As[ak0 + 3][r] = v.w;
        }
        {
            float4 v = *(const float4*)(W + (size_t)(n0 + ar0) * ldw + k0 + ak0);
            Bs[ak0 + 0][ar0] = v.x; Bs[ak0 + 1][ar0] = v.y; Bs[ak0 + 2][ar0] = v.z; Bs[ak0 + 3][ar0] = v.w;
        }
        __syncthreads();
#pragma unroll
        for (int kk = 0; kk < GBK; kk++) {
            float a[8], b[4];
#pragma unroll
            for (int i = 0; i < 8; i++) a[i] = As[kk][ty * 8 + i];
#pragma unroll
            for (int j = 0; j < 4; j++) b[j] = Bs[kk][tx * 4 + j];
#pragma unroll
            for (int i = 0; i < 8; i++)
#pragma unroll
                for (int j = 0; j < 4; j++) acc[i][j] = fmaf(a[i], b[j], acc[i][j]);
        }
        __syncthreads();
    }
    float b4[4];
#pragma unroll
    for (int j = 0; j < 4; j++) b4[j] = bias[n0 + tx * 4 + j];
#pragma unroll
    for (int i = 0; i < 8; i++) {
        int m = m0 + ty * 8 + i;
        if (TR == 1) {
            int bb = m / sdim, s = m % sdim;
#pragma unroll
            for (int j = 0; j < 4; j++)
                C[((size_t)s * G3 + n0 + tx * 4 + j) * B + bb] = acc[i][j] + b4[j];
        } else if (TR == 2) {
            int bb = m / sdim, s = m % sdim;
#pragma unroll
            for (int j = 0; j < 4; j++)
                C[((size_t)bb * G3 + n0 + tx * 4 + j) * sdim + s] = acc[i][j] + b4[j];
        } else {
            float4 o;
            o.x = acc[i][0] + b4[0]; o.y = acc[i][1] + b4[1];
            o.z = acc[i][2] + b4[2]; o.w = acc[i][3] + b4[3];
            *(float4*)(C + (size_t)m * ldc + n0 + tx * 4) = o;
        }
    }
}

// ---------------- persistent encoder (R9-proven) ----------------
extern __shared__ float4 sdyn[];
__global__ __launch_bounds__(128) void enc_persist(
    const float* __restrict__ Whh_f, const float* __restrict__ bhh_f,
    const float* __restrict__ Whh_b, const float* __restrict__ bhh_b,
    const int* __restrict__ src_lengths)
{
    float4* sW = sdyn;
    float4* sH = sdyn + 3072;
    int tid = threadIdx.x, lane = tid & 31, w = tid >> 5, bx = blockIdx.x;
    int dir = bx >> 6, j0c = (bx & 63) * 8;
    const float* Whh = dir ? Whh_b : Whh_f;
    const float* bhh = dir ? bhh_b : bhh_f;
    const float* gx = dir ? g_gxb : g_gxf;
    float* hbuf0 = dir ? g_hTb[0] : g_hTf[0];
    float* hbuf1 = dir ? g_hTb[1] : g_hTf[1];
    int len = src_lengths[lane];

    for (int idx = tid; idx < 3072; idx += 128) {
        int g = idx >> 10, rem = idx & 1023, jj = rem >> 7, k4 = rem & 127;
        sW[idx] = ((const float4*)(Whh + (size_t)(g * H + j0c + jj) * H))[k4];
    }
    int jj0 = w * 2, j0 = j0c + jj0;
    float br0 = bhh[j0],     bz0 = bhh[H + j0],     bn0 = bhh[2 * H + j0];
    float br1 = bhh[j0 + 1], bz1 = bhh[H + j0 + 1], bn1 = bhh[2 * H + j0 + 1];
    const float4* base = sW + jj0 * 128;
    unsigned bt = 0;

    for (int i = 0; i < S; i++) {
        int t = dir ? (S - 1 - i) : i;
        const float* hin = (i & 1) ? hbuf1 : hbuf0;
        float* hout = (i & 1) ? hbuf0 : hbuf1;
        __syncthreads();
        for (int idx = tid; idx < 4096; idx += 128)
            sH[idx] = ((const float4*)hin)[idx];
        __syncthreads();

        float ar0 = br0, az0 = bz0, an0 = bn0, ar1 = br1, az1 = bz1, an1 = bn1;
#pragma unroll 4
        for (int k4 = 0; k4 < 128; k4++) {
            float4 h4 = sH[k4 * B + lane];
            float4 r0 = base[k4],        r1 = base[k4 + 128];
            float4 z0 = base[k4 + 1024], z1 = base[k4 + 1152];
            float4 n0 = base[k4 + 2048], n1 = base[k4 + 2176];
            ar0 = fmaf(r0.x, h4.x, ar0); ar0 = fmaf(r0.y, h4.y, ar0); ar0 = fmaf(r0.z, h4.z, ar0); ar0 = fmaf(r0.w, h4.w, ar0);
            ar1 = fmaf(r1.x, h4.x, ar1); ar1 = fmaf(r1.y, h4.y, ar1); ar1 = fmaf(r1.z, h4.z, ar1); ar1 = fmaf(r1.w, h4.w, ar1);
            az0 = fmaf(z0.x, h4.x, az0); az0 = fmaf(z0.y, h4.y, az0); az0 = fmaf(z0.z, h4.z, az0); az0 = fmaf(z0.w, h4.w, az0);
            az1 = fmaf(z1.x, h4.x, az1); az1 = fmaf(z1.y, h4.y, az1); az1 = fmaf(z1.z, h4.z, az1); az1 = fmaf(z1.w, h4.w, az1);
            an0 = fmaf(n0.x, h4.x, an0); an0 = fmaf(n0.y, h4.y, an0); an0 = fmaf(n0.z, h4.z, an0); an0 = fmaf(n0.w, h4.w, an0);
            an1 = fmaf(n1.x, h4.x, an1); an1 = fmaf(n1.y, h4.y, an1); an1 = fmaf(n1.z, h4.z, an1); an1 = fmaf(n1.w, h4.w, an1);
        }
        int mask = t < len;
        const float* gxt = gx + (size_t)t * G3 * B;
#pragma unroll
        for (int jj = 0; jj < 2; jj++) {
            int j = j0 + jj;
            float ar = jj ? ar1 : ar0, az = jj ? az1 : az0, an = jj ? an1 : an0;
            float r = sigm(gxt[(size_t)j * B + lane] + ar);
            float z = sigm(gxt[(size_t)(H + j) * B + lane] + az);
            float n = tanhf(gxt[(size_t)(2 * H + j) * B + lane] + r * an);
            int hidx = (j >> 2) * (B * 4) + lane * 4 + (j & 3);
            float hprev = ((const float*)sH)[hidx];
            float hnew = (1.f - z) * n + z * hprev;
            hout[hidx] = mask ? hnew : hprev;
            g_srchid[(size_t)(lane * S + t) * (2 * H) + dir * H + j] = mask ? hnew : 0.f;
        }
        if (i < S - 1) bar_sync(&g_cnt_enc[0], (++bt) * ENC_BLOCKS);
    }
}

// ---------------- persistent decoder with P-trick (R12-proven; abf fused) ----------------
__global__ __launch_bounds__(128) void dec_persist(
    const float* __restrict__ dec_Whh, const float* __restrict__ dec_bhh,
    const float* __restrict__ A_W, const float* __restrict__ A_b,
    const float* __restrict__ A_v,
    const int* __restrict__ src_lengths, const int* __restrict__ tgt_lengths)
{
    float4* sW1 = sdyn;
    float4* sH  = sdyn + 2048;
    __shared__ float se[S];
    __shared__ float sAl[S * 33];
    int tid = threadIdx.x, lane = tid & 31, w = tid >> 5, bx = blockIdx.x;
    int jh = bx * 4 + w;

    for (int idx = tid; idx < 2048; idx += 128) {
        int slot = idx >> 7, k4 = idx & 127;
        const float* src;
        if (slot < 12) src = dec_Whh + (size_t)((slot >> 2) * 512 + bx * 4 + (slot & 3)) * H;
        else           src = A_W + (size_t)(bx * 4 + (slot - 12)) * H;
        sW1[idx] = ((const float4*)src)[k4];
    }
    float bhr = dec_bhh[jh], bhz = dec_bhh[512 + jh], bhn = dec_bhh[1024 + jh];
    float ba  = A_b[jh];
    int len2 = src_lengths[bx & 31];
    float av[16];
#pragma unroll
    for (int m = 0; m < 16; m++) av[m] = A_v[lane + m * 32];
    int mylen = tgt_lengths[lane];
    const float4* wR = sW1 + (0 + w) * 128;
    const float4* wZ = sW1 + (4 + w) * 128;
    const float4* wN = sW1 + (8 + w) * 128;
    const float4* wA = sW1 + (12 + w) * 128;
    const float* Pr = g_P + ((size_t)lane * G3 + jh) * S;
    const float* Pz = Pr + (size_t)512 * S;
    const float* Pn = Pr + (size_t)1024 * S;
    unsigned bt = 0;

    for (int i = 0; i < T; i++) {
        float ghr, ghz, ghn;
        {
            const float* hin = g_hTd[i & 1];
            __syncthreads();
            for (int idx = tid; idx < 4096; idx += 128)
                sH[idx] = ((const float4*)hin)[idx];
            __syncthreads();
            float aR = bhr, aZ = bhz, aN = bhn, aA = ba;
#pragma unroll 4
            for (int k4 = 0; k4 < 128; k4++) {
                float4 h4 = sH[k4 * B + lane];
                float4 r4 = wR[k4], z4 = wZ[k4], n4 = wN[k4], a4 = wA[k4];
                aR = fmaf(r4.x, h4.x, aR); aR = fmaf(r4.y, h4.y, aR); aR = fmaf(r4.z, h4.z, aR); aR = fmaf(r4.w, h4.w, aR);
                aZ = fmaf(z4.x, h4.x, aZ); aZ = fmaf(z4.y, h4.y, aZ); aZ = fmaf(z4.z, h4.z, aZ); aZ = fmaf(z4.w, h4.w, aZ);
                aN = fmaf(n4.x, h4.x, aN); aN = fmaf(n4.y, h4.y, aN); aN = fmaf(n4.z, h4.z, aN); aN = fmaf(n4.w, h4.w, aN);
                aA = fmaf(a4.x, h4.x, aA); aA = fmaf(a4.y, h4.y, aA); aA = fmaf(a4.z, h4.z, aA); aA = fmaf(a4.w, h4.w, aA);
            }
            ghr = aR; ghz = aZ; ghn = aN;
            g_Ah[lane * H + jh] = aA;
        }
        bar_sync(&g_cnt_dec[0], (++bt) * DEC_BLOCKS);

        if (bx < 32) {
            int b2 = bx;
            float ah[16];
#pragma unroll
            for (int m = 0; m < 16; m++) ah[m] = g_Ah[b2 * H + lane + m * 32];
#pragma unroll
            for (int si = 0; si < 16; si++) {
                int s = w * 16 + si;
                const float* uh = g_Uh + (size_t)(b2 * S + s) * H;
                float p = 0.f;
#pragma unroll
                for (int m = 0; m < 16; m++)
                    p = fmaf(av[m], tanh_fast(uh[lane + m * 32] + ah[m]), p);
#pragma unroll
                for (int off = 16; off; off >>= 1) p += __shfl_xor_sync(0xffffffffu, p, off);
                if (lane == 0) se[s] = (s < len2) ? p : -1e9f;
            }
            __syncthreads();
            if (w == 0) {
                float e0 = se[lane], e1 = se[lane + 32];
                float m = fmaxf(e0, e1);
#pragma unroll
                for (int off = 16; off; off >>= 1) m = fmaxf(m, __shfl_xor_sync(0xffffffffu, m, off));
                float x0 = __expf(e0 - m), x1 = __expf(e1 - m);
                float sm = x0 + x1;
#pragma unroll
                for (int off = 16; off; off >>= 1) sm += __shfl_xor_sync(0xffffffffu, sm, off);
                float inv = 1.0f / sm;
                g_alpha[b2 * S + lane] = x0 * inv;
                g_alpha[b2 * S + lane + 32] = x1 * inv;
            }
        }
        bar_sync(&g_cnt_dec[0], (++bt) * DEC_BLOCKS);

        {
            for (int idx = tid; idx < B * S; idx += 128) {
                int s = idx >> 5, b = idx & 31;
                sAl[s * 33 + b] = g_alpha[b * S + s];
            }
            __syncthreads();
            float ar = 0.f, az = 0.f, an = 0.f;
#pragma unroll 8
            for (int s = 0; s < S; s++) {
                float a = sAl[s * 33 + lane];
                ar = fmaf(a, Pr[s], ar);
                az = fmaf(a, Pz[s], az);
                an = fmaf(a, Pn[s], an);
            }
            const float* gxt = g_gxemb + (size_t)i * G3 * B;
            float gxr = gxt[(size_t)jh * B + lane] + ar;
            float gxz = gxt[(size_t)(512 + jh) * B + lane] + az;
            float gxn = gxt[(size_t)(1024 + jh) * B + lane] + an;
            float r = sigm(gxr + ghr);
            float z = sigm(gxz + ghz);
            float n = tanhf(gxn + r * ghn);
            int hidx = (jh >> 2) * (B * 4) + lane * 4 + (jh & 3);
            float hprev = g_hTd[i & 1][hidx];
            float hnew = (1.f - z) * n + z * hprev;
            int mask = i < mylen;
            g_hTd[(i + 1) & 1][hidx] = mask ? hnew : hprev;
            g_abf[(size_t)(lane * T + i) * H + jh] = __float2bfloat16(mask ? hnew : 0.f);
            __syncthreads();
        }
        if (i < T - 1) bar_sync(&g_cnt_dec[0], (++bt) * DEC_BLOCKS);
    }
}

__global__ __launch_bounds__(256) void cvt_bf16(const float* __restrict__ src,
                                                __nv_bfloat16* __restrict__ dst, int n8)
{
    int i = blockIdx.x * 256 + threadIdx.x;
    if (i < n8) {
        float4 a = ((const float4*)src)[i * 2], b = ((const float4*)src)[i * 2 + 1];
        __nv_bfloat162 o[4];
        o[0] = __nv_bfloat162(__float2bfloat16(a.x), __float2bfloat16(a.y));
        o[1] = __nv_bfloat162(__float2bfloat16(a.z), __float2bfloat16(a.w));
        o[2] = __nv_bfloat162(__float2bfloat16(b.x), __float2bfloat16(b.y));
        o[3] = __nv_bfloat162(__float2bfloat16(b.z), __float2bfloat16(b.w));
        ((uint4*)dst)[i] = *(uint4*)o;
    }
}

// ---------------- bf16 mma logits GEMM (pipelined) + fused per-tile online LSE ----------------
#define LBM 128
#define LBN 128
#define LBK 32
#define LPAD 8
__device__ __forceinline__ void mma16816(float* d, const unsigned* a, const unsigned* b) {
    asm volatile("mma.sync.aligned.m16n8k16.row.col.f32.bf16.bf16.f32 "
        "{%0,%1,%2,%3},{%4,%5,%6,%7},{%8,%9},{%0,%1,%2,%3};"
        : "+f"(d[0]), "+f"(d[1]), "+f"(d[2]), "+f"(d[3])
        : "r"(a[0]), "r"(a[1]), "r"(a[2]), "r"(a[3]), "r"(b[0]), "r"(b[1]));
}
__global__ __launch_bounds__(256) void gemm_logits(const float* __restrict__ out_b)
{
    __shared__ __nv_bfloat16 As[LBM][LBK + LPAD];
    __shared__ __nv_bfloat16 Ws[LBN][LBK + LPAD];
    __shared__ float smM[LBM][4], smS[LBM][4];
    int tid = threadIdx.x;
    int m0 = blockIdx.y * LBM, n0 = blockIdx.x * LBN;
    int wid = tid >> 5, lane = tid & 31;
    int wm = (wid & 1) * 64, wn = (wid >> 1) * 32;
    float acc[4][4][4];
#pragma unroll
    for (int a = 0; a < 4; a++)
#pragma unroll
        for (int b = 0; b < 4; b++)
#pragma unroll
            for (int c = 0; c < 4; c++) acc[a][b][c] = 0.f;

    int lr = tid >> 1, lc = (tid & 1) * 16;
    const __nv_bfloat16* Aptr = g_abf + (size_t)(m0 + lr) * H + lc;
    const __nv_bfloat16* Wptr = g_wbf + (size_t)(n0 + lr) * H + lc;
    uint4 va  = *(const uint4*)(Aptr);
    uint4 va2 = *(const uint4*)(Aptr + 8);
    uint4 vw  = *(const uint4*)(Wptr);
    uint4 vw2 = *(const uint4*)(Wptr + 8);

    for (int k0 = 0; k0 < H; k0 += LBK) {
        __syncthreads();
        *(uint4*)&As[lr][lc] = va;  *(uint4*)&As[lr][lc + 8] = va2;
        *(uint4*)&Ws[lr][lc] = vw;  *(uint4*)&Ws[lr][lc + 8] = vw2;
        __syncthreads();
        if (k0 + LBK < H) {   // prefetch next slab; latency hides behind MMA below
            va  = *(const uint4*)(Aptr + k0 + LBK);
            va2 = *(const uint4*)(Aptr + k0 + LBK + 8);
            vw  = *(const uint4*)(Wptr + k0 + LBK);
            vw2 = *(const uint4*)(Wptr + k0 + LBK + 8);
        }
#pragma unroll
        for (int kk = 0; kk < LBK; kk += 16) {
            unsigned af[4][4], bfr[4][2];
            int arow = lane >> 2, acol = kk + (lane & 3) * 2;
#pragma unroll
            for (int mf = 0; mf < 4; mf++) {
                af[mf][0] = *(const unsigned*)&As[wm + mf * 16 + arow][acol];
                af[mf][1] = *(const unsigned*)&As[wm + mf * 16 + arow + 8][acol];
                af[mf][2] = *(const unsigned*)&As[wm + mf * 16 + arow][acol + 8];
                af[mf][3] = *(const unsigned*)&As[wm + mf * 16 + arow + 8][acol + 8];
            }
#pragma unroll
            for (int nf = 0; nf < 4; nf++) {
                int brow = wn + nf * 8 + (lane >> 2);
                bfr[nf][0] = *(const unsigned*)&Ws[brow][acol];
                bfr[nf][1] = *(const unsigned*)&Ws[brow][acol + 8];
            }
#pragma unroll
            for (int mf = 0; mf < 4; mf++)
#pragma unroll
                for (int nf = 0; nf < 4; nf++) mma16816(acc[mf][nf], af[mf], bfr[nf]);
        }
    }
    // ---- fused per-row online LSE over this 128-col tile ----
    float bb[4][2];
#pragma unroll
    for (int nf = 0; nf < 4; nf++) {
        int n = n0 + wn + nf * 8 + (lane & 3) * 2;
        bb[nf][0] = out_b[n]; bb[nf][1] = out_b[n + 1];
    }
    __syncthreads();
#pragma unroll
    for (int half = 0; half < 2; half++) {
#pragma unroll
        for (int mf = 0; mf < 4; mf++) {
            float m = -1e30f, s = 0.f;
#pragma unroll
            for (int nf = 0; nf < 4; nf++) {
#pragma unroll
                for (int c = 0; c < 2; c++) {
                    float x = acc[mf][nf][half * 2 + c] + bb[nf][c];
                    if (x > m) { s = s * __expf(m - x) + 1.f; m = x; }
                    else s += __expf(x - m);
                }
            }
#pragma unroll
            for (int off = 1; off < 4; off <<= 1) {
                float m2 = __shfl_xor_sync(0xffffffffu, m, off);
                float s2 = __shfl_xor_sync(0xffffffffu, s, off);
                float mm = fmaxf(m, m2);
                s = s * __expf(m - mm) + s2 * __expf(m2 - mm);
                m = mm;
            }
            if ((lane & 3) == 0) {
                int rr = wm + mf * 16 + (lane >> 2) + 8 * half;
                smM[rr][wid >> 1] = m; smS[rr][wid >> 1] = s;
            }
        }
    }
    __syncthreads();
    if (tid < LBM) {
        float m = smM[tid][0], s = smS[tid][0];
#pragma unroll
        for (int q = 1; q < 4; q++) {
            float m2 = smM[tid][q], s2 = smS[tid][q];
            float mm = fmaxf(m, m2);
            s = s * __expf(m - mm) + s2 * __expf(m2 - mm);
            m = mm;
        }
        g_pm[(size_t)(m0 + tid) * NB + blockIdx.x] = m;
        g_ps[(size_t)(m0 + tid) * NB + blockIdx.x] = s;
    }
}

// ---------------- merge partials + picked logit ----------------
__global__ __launch_bounds__(256) void merge_lse(
    const int* __restrict__ tgt_seqs, const float* __restrict__ out_b)
{
    int row = blockIdx.x, b = row / T, t = row % T;
    int tid = threadIdx.x;
    int goal = (t < T - 1) ? tgt_seqs[b * T + t + 1] : 0;
    __shared__ float sm_[256], ss_[256];
    float m = -1e30f, s = 0.f;
    if (tid < NB) { m = g_pm[(size_t)row * NB + tid]; s = g_ps[(size_t)row * NB + tid]; }
    sm_[tid] = m; ss_[tid] = s; __syncthreads();
    for (int q = 128; q; q >>= 1) {
        if (tid < q) {
            float m1 = sm_[tid], s1 = ss_[tid], m2 = sm_[tid + q], s2 = ss_[tid + q];
            float mm = fmaxf(m1, m2);
            sm_[tid] = mm; ss_[tid] = s1 * __expf(m1 - mm) + s2 * __expf(m2 - mm);
        }
        __syncthreads();
    }
    float lse = sm_[0] + logf(ss_[0]);
    float p = 0.f;
    if (goal != 0) {
        for (int k = tid; k < H; k += 256)
            p += __bfloat162float(g_abf[(size_t)row * H + k]) *
                 __bfloat162float(g_wbf[(size_t)goal * H + k]);
    }
    __syncthreads();
    sm_[tid] = p; __syncthreads();
    for (int q = 128; q; q >>= 1) {
        if (tid < q) sm_[tid] += sm_[tid + q];
        __syncthreads();
    }
    if (tid == 0)
        g_rowres[row] = (goal != 0) ? (sm_[0] + out_b[goal] - lse) : 0.f;
}

__global__ __launch_bounds__(256) void final_loss(
    const int* __restrict__ tgt_seqs, float* __restrict__ out)
{
    __shared__ float sp[256], sc[256];
    int tid = threadIdx.x;
    float ps = 0.f, pc = 0.f;
    for (int r = tid; r < B * T; r += 256) {
        ps += g_rowres[r];
        int b = r / T, t = r % T;
        int goal = (t < T - 1) ? tgt_seqs[b * T + t + 1] : 0;
        pc += (goal != 0) ? 1.f : 0.f;
    }
    sp[tid] = ps; sc[tid] = pc; __syncthreads();
    for (int q = 128; q; q >>= 1) {
        if (tid < q) { sp[tid] += sp[tid + q]; sc[tid] += sc[tid + q]; }
        __syncthreads();
    }
    if (tid == 0) out[0] = -sp[0] / sc[0];
}

extern "C" void kernel_launch(void* const* d_in, const int* in_sizes, int n_in,
                              void* d_out, int out_size)
{
    const int* src_seqs    = (const int*)d_in[0];
    const int* src_lengths = (const int*)d_in[1];
    const int* tgt_seqs    = (const int*)d_in[2];
    const int* tgt_lengths = (const int*)d_in[3];
    const float* src_emb   = (const float*)d_in[4];
    const float* enc_Wih_f = (const float*)d_in[5];
    const float* enc_Whh_f = (const float*)d_in[6];
    const float* enc_bih_f = (const float*)d_in[7];
    const float* enc_bhh_f = (const float*)d_in[8];
    const float* enc_Wih_b = (const float*)d_in[9];
    const float* enc_Whh_b = (const float*)d_in[10];
    const float* enc_bih_b = (const float*)d_in[11];
    const float* enc_bhh_b = (const float*)d_in[12];
    const float* tgt_emb   = (const float*)d_in[13];
    const float* dec_Wih   = (const float*)d_in[14];
    const float* dec_Whh   = (const float*)d_in[15];
    const float* dec_bih   = (const float*)d_in[16];
    const float* dec_bhh   = (const float*)d_in[17];
    const float* U_w       = (const float*)d_in[18];
    const float* U_b       = (const float*)d_in[19];
    const float* A_W       = (const float*)d_in[20];
    const float* A_b       = (const float*)d_in[21];
    const float* A_v       = (const float*)d_in[22];
    const float* out_w     = (const float*)d_in[23];
    const float* out_b     = (const float*)d_in[24];

    void *p_esrc, *p_etgt, *p_gxf, *p_gxb, *p_gxemb, *p_srchid, *p_Uh, *p_P, *p_wbf, *p_zb;
    cudaGetSymbolAddress(&p_esrc, g_esrc);
    cudaGetSymbolAddress(&p_etgt, g_etgt);
    cudaGetSymbolAddress(&p_gxf, g_gxf);
    cudaGetSymbolAddress(&p_gxb, g_gxb);
    cudaGetSymbolAddress(&p_gxemb, g_gxemb);
    cudaGetSymbolAddress(&p_srchid, g_srchid);
    cudaGetSymbolAddress(&p_Uh, g_Uh);
    cudaGetSymbolAddress(&p_P, g_P);
    cudaGetSymbolAddress(&p_wbf, g_wbf);
    cudaGetSymbolAddress(&p_zb, g_zb);

    const int enc_smem = (3072 + 4096) * 16;
    const int dec_smem = (2048 + 4096) * 16;
    cudaFuncSetAttribute(enc_persist, cudaFuncAttributeMaxDynamicSharedMemorySize, enc_smem);
    cudaFuncSetAttribute(dec_persist, cudaFuncAttributeMaxDynamicSharedMemorySize, dec_smem);

    zero_h_kernel<<<(H * B + 255) / 256, 256>>>();
    embed_kernel<<<B * S + B * T, 128>>>(src_seqs, tgt_seqs, src_emb, tgt_emb);

    // wbf conversion early (independent of recurrence; overlaps nothing but fills the gap)
    cvt_bf16<<<((int)((size_t)V * H / 8) + 255) / 256, 256>>>(out_w,
                                                   (__nv_bfloat16*)p_wbf, (int)((size_t)V * H / 8));

    gemm_nt<1><<<dim3(G3 / GBN, (B * S) / GBM), 256>>>(
        (const float*)p_esrc, E, enc_Wih_f, E, enc_bih_f, (float*)p_gxf, G3, E, S);
    gemm_nt<1><<<dim3(G3 / GBN, (B * S) / GBM), 256>>>(
        (const float*)p_esrc, E, enc_Wih_b, E, enc_bih_b, (float*)p_gxb, G3, E, S);
    gemm_nt<1><<<dim3(G3 / GBN, (B * T) / GBM), 256>>>(
        (const float*)p_etgt, E, dec_Wih, G3, dec_bih, (float*)p_gxemb, G3, E, T);

    enc_persist<<<ENC_BLOCKS, 128, enc_smem>>>(enc_Whh_f, enc_bhh_f, enc_Whh_b, enc_bhh_b, src_lengths);

    gemm_nt<0><<<dim3(H / GBN, (B * S) / GBM), 256>>>(
        (const float*)p_srchid, 2 * H, U_w, 2 * H, U_b, (float*)p_Uh, H, 2 * H, S);
    gemm_nt<2><<<dim3(G3 / GBN, (B * S) / GBM), 256>>>(
        (const float*)p_srchid, 2 * H, dec_Wih + 512, G3, (const float*)p_zb, (float*)p_P, 0, 2 * H, S);

    dec_persist<<<DEC_BLOCKS, 128, dec_smem>>>(dec_Whh, dec_bhh, A_W, A_b, A_v,
                                               src_lengths, tgt_lengths);

    gemm_logits<<<dim3(V / LBN, (B * T) / LBM), 256>>>(out_b);
    merge_lse<<<B * T, 256>>>(tgt_seqs, out_b);
    final_loss<<<1, 256>>>(tgt_seqs, (float*)d_out);
}

// round 16
// speedup vs baseline: 1.0862x; 1.0862x over previous
#include <cuda_runtime.h>
#include <cuda_bf16.h>
#include <cstdint>
#include <math.h>

#define B 32
#define S 64
#define T 64
#define E 512
#define H 512
#define V 32000
#define G3 1536
#define NB 250          // V / 128 partial tiles

#define ENC_BLOCKS 128
#define DEC_BLOCKS 128

__device__ float g_esrc[B * S * E];
__device__ float g_etgt[B * T * E];
__device__ float g_gxf[B * S * G3];
__device__ float g_gxb[B * S * G3];
__device__ float g_gxemb[B * T * G3];
__device__ float g_srchid[B * S * 2 * H];
__device__ float g_Uh[B * S * H];
__device__ float g_P[(size_t)B * G3 * S];
__device__ float g_hTf[2][H * B];
__device__ float g_hTb[2][H * B];
__device__ float g_hTd[2][H * B];
__device__ float g_Ah[B * H];
__device__ float g_alpha[B * S];
__device__ float g_pm[B * T * NB];
__device__ float g_ps[B * T * NB];
__device__ float g_rowres[B * T];
__device__ float g_zb[G3];
__device__ __nv_bfloat16 g_wbf[(size_t)V * H];
__device__ __nv_bfloat16 g_abf[B * T * H];
__device__ unsigned g_cnt_enc[32];
__device__ unsigned g_cnt_dec[32];

__device__ __forceinline__ float sigm(float x) { return 1.0f / (1.0f + expf(-x)); }
__device__ __forceinline__ float tanh_fast(float x) {
    float y; asm("tanh.approx.f32 %0, %1;" : "=f"(y) : "f"(x)); return y;
}
__device__ __forceinline__ void bar_sync(unsigned* cnt, unsigned target) {
    __syncthreads();
    if (threadIdx.x == 0) {
        asm volatile("fence.acq_rel.gpu;" ::: "memory");
        asm volatile("red.relaxed.gpu.add.u32 [%0], 1;" :: "l"(cnt) : "memory");
        unsigned v;
        do {
            asm volatile("ld.relaxed.gpu.u32 %0, [%1];" : "=r"(v) : "l"(cnt) : "memory");
        } while (v < target);
        asm volatile("fence.acq_rel.gpu;" ::: "memory");
    }
    __syncthreads();
}

__global__ void zero_h_kernel() {
    int idx = blockIdx.x * blockDim.x + threadIdx.x;
    if (idx < H * B) { g_hTf[0][idx] = 0.f; g_hTb[0][idx] = 0.f; g_hTd[0][idx] = 0.f; }
    if (idx < G3) g_zb[idx] = 0.f;
    if (idx == 0) { g_cnt_enc[0] = 0; g_cnt_dec[0] = 0; }
}

__global__ __launch_bounds__(128) void embed_kernel(
    const int* __restrict__ src_seqs, const int* __restrict__ tgt_seqs,
    const float* __restrict__ src_emb, const float* __restrict__ tgt_emb)
{
    int blk = blockIdx.x, tid = threadIdx.x;
    if (blk < B * S) {
        int tok = src_seqs[blk];
        ((float4*)(g_esrc + (size_t)blk * E))[tid] = ((const float4*)(src_emb + (size_t)tok * E))[tid];
    } else {
        int r = blk - B * S;
        int tok = tgt_seqs[r];
        ((float4*)(g_etgt + (size_t)r * E))[tid] = ((const float4*)(tgt_emb + (size_t)tok * E))[tid];
    }
}

// ---- fp32 GEMM: C=A@W^T+bias; TR=0 row-major, TR=1 [s][n][b], TR=2 [b][n][s] ----
#define GBM 128
#define GBN 64
#define GBK 16
template<int TR>
__global__ __launch_bounds__(256) void gemm_nt(
    const float* __restrict__ A, int lda,
    const float* __restrict__ W, int ldw,
    const float* __restrict__ bias,
    float* __restrict__ C, int ldc, int K, int sdim)
{
    __shared__ float As[GBK][GBM];
    __shared__ float Bs[GBK][GBN];
    int tid = threadIdx.x;
    int m0 = blockIdx.y * GBM, n0 = blockIdx.x * GBN;
    int tx = tid & 15, ty = tid >> 4;
    float acc[8][4];
#pragma unroll
    for (int i = 0; i < 8; i++)
#pragma unroll
        for (int j = 0; j < 4; j++) acc[i][j] = 0.f;
    int ar0 = tid >> 2, ak0 = (tid & 3) * 4;
    for (int k0 = 0; k0 < K; k0 += GBK) {
#pragma unroll
        for (int h = 0; h < 2; h++) {
            int r = ar0 + h * 64;
            float4 v = *(const float4*)(A + (size_t)(m0 + r) * lda + k0 + ak0);
            As[ak0 + 0][r] = v.x; As[ak0 + 1][r] = v.y; As[ak0 + 2][r] = v.z; As[ak0 + 3][r] = v.w;
        }
        {
            float4 v = *(const float4*)(W + (size_t)(n0 + ar0) * ldw + k0 + ak0);
            Bs[ak0 + 0][ar0] = v.x; Bs[ak0 + 1][ar0] = v.y; Bs[ak0 + 2][ar0] = v.z; Bs[ak0 + 3][ar0] = v.w;
        }
        __syncthreads();
#pragma unroll
        for (int kk = 0; kk < GBK; kk++) {
            float a[8], b[4];
#pragma unroll
            for (int i = 0; i < 8; i++) a[i] = As[kk][ty * 8 + i];
#pragma unroll
            for (int j = 0; j < 4; j++) b[j] = Bs[kk][tx * 4 + j];
#pragma unroll
            for (int i = 0; i < 8; i++)
#pragma unroll
                for (int j = 0; j < 4; j++) acc[i][j] = fmaf(a[i], b[j], acc[i][j]);
        }
        __syncthreads();
    }
    float b4[4];
#pragma unroll
    for (int j = 0; j < 4; j++) b4[j] = bias[n0 + tx * 4 + j];
#pragma unroll
    for (int i = 0; i < 8; i++) {
        int m = m0 + ty * 8 + i;
        if (TR == 1) {
            int bb = m / sdim, s = m % sdim;
#pragma unroll
            for (int j = 0; j < 4; j++)
                C[((size_t)s * G3 + n0 + tx * 4 + j) * B + bb] = acc[i][j] + b4[j];
        } else if (TR == 2) {
            int bb = m / sdim, s = m % sdim;
#pragma unroll
            for (int j = 0; j < 4; j++)
                C[((size_t)bb * G3 + n0 + tx * 4 + j) * sdim + s] = acc[i][j] + b4[j];
        } else {
            float4 o;
            o.x = acc[i][0] + b4[0]; o.y = acc[i][1] + b4[1];
            o.z = acc[i][2] + b4[2]; o.w = acc[i][3] + b4[3];
            *(float4*)(C + (size_t)m * ldc + n0 + tx * 4) = o;
        }
    }
}

// ---------------- persistent encoder: 256 threads, 1 j per warp ----------------
extern __shared__ float4 sdyn[];
__global__ __launch_bounds__(256) void enc_persist(
    const float* __restrict__ Whh_f, const float* __restrict__ bhh_f,
    const float* __restrict__ Whh_b, const float* __restrict__ bhh_b,
    const int* __restrict__ src_lengths)
{
    float4* sW = sdyn;          // 3072 f4: [gate][jj 0..7][k4 0..127]
    float4* sH = sdyn + 3072;   // 4096 f4: f4 idx k4*B + b
    int tid = threadIdx.x, lane = tid & 31, w = tid >> 5, bx = blockIdx.x;
    int dir = bx >> 6, j0c = (bx & 63) * 8;
    const float* Whh = dir ? Whh_b : Whh_f;
    const float* bhh = dir ? bhh_b : bhh_f;
    const float* gx = dir ? g_gxb : g_gxf;
    float* hbuf0 = dir ? g_hTb[0] : g_hTf[0];
    float* hbuf1 = dir ? g_hTb[1] : g_hTf[1];
    int len = src_lengths[lane];

    for (int idx = tid; idx < 3072; idx += 256) {
        int g = idx >> 10, rem = idx & 1023, jj = rem >> 7, k4 = rem & 127;
        sW[idx] = ((const float4*)(Whh + (size_t)(g * H + j0c + jj) * H))[k4];
    }
    int j = j0c + w;                 // w in [0,8): one j per warp
    float br = bhh[j], bz = bhh[H + j], bn = bhh[2 * H + j];
    const float4* base = sW + w * 128;
    unsigned bt = 0;

    for (int i = 0; i < S; i++) {
        int t = dir ? (S - 1 - i) : i;
        const float* hin = (i & 1) ? hbuf1 : hbuf0;
        float* hout = (i & 1) ? hbuf0 : hbuf1;
        __syncthreads();
        for (int idx = tid; idx < 4096; idx += 256)
            sH[idx] = ((const float4*)hin)[idx];
        __syncthreads();

        float ar = br, az = bz, an = bn;
#pragma unroll 8
        for (int k4 = 0; k4 < 128; k4++) {
            float4 h4 = sH[k4 * B + lane];
            float4 r4 = base[k4];
            float4 z4 = base[k4 + 1024];
            float4 n4 = base[k4 + 2048];
            ar = fmaf(r4.x, h4.x, ar); ar = fmaf(r4.y, h4.y, ar); ar = fmaf(r4.z, h4.z, ar); ar = fmaf(r4.w, h4.w, ar);
            az = fmaf(z4.x, h4.x, az); az = fmaf(z4.y, h4.y, az); az = fmaf(z4.z, h4.z, az); az = fmaf(z4.w, h4.w, az);
            an = fmaf(n4.x, h4.x, an); an = fmaf(n4.y, h4.y, an); an = fmaf(n4.z, h4.z, an); an = fmaf(n4.w, h4.w, an);
        }
        int mask = t < len;
        const float* gxt = gx + (size_t)t * G3 * B;
        float r = sigm(gxt[(size_t)j * B + lane] + ar);
        float z = sigm(gxt[(size_t)(H + j) * B + lane] + az);
        float n = tanhf(gxt[(size_t)(2 * H + j) * B + lane] + r * an);
        int hidx = (j >> 2) * (B * 4) + lane * 4 + (j & 3);
        float hprev = ((const float*)sH)[hidx];
        float hnew = (1.f - z) * n + z * hprev;
        hout[hidx] = mask ? hnew : hprev;
        g_srchid[(size_t)(lane * S + t) * (2 * H) + dir * H + j] = mask ? hnew : 0.f;
        if (i < S - 1) bar_sync(&g_cnt_enc[0], (++bt) * ENC_BLOCKS);
    }
}

// ---------------- persistent decoder with P-trick (R12/R15-proven) ----------------
__global__ __launch_bounds__(128) void dec_persist(
    const float* __restrict__ dec_Whh, const float* __restrict__ dec_bhh,
    const float* __restrict__ A_W, const float* __restrict__ A_b,
    const float* __restrict__ A_v,
    const int* __restrict__ src_lengths, const int* __restrict__ tgt_lengths)
{
    float4* sW1 = sdyn;
    float4* sH  = sdyn + 2048;
    __shared__ float se[S];
    __shared__ float sAl[S * 33];
    int tid = threadIdx.x, lane = tid & 31, w = tid >> 5, bx = blockIdx.x;
    int jh = bx * 4 + w;

    for (int idx = tid; idx < 2048; idx += 128) {
        int slot = idx >> 7, k4 = idx & 127;
        const float* src;
        if (slot < 12) src = dec_Whh + (size_t)((slot >> 2) * 512 + bx * 4 + (slot & 3)) * H;
        else           src = A_W + (size_t)(bx * 4 + (slot - 12)) * H;
        sW1[idx] = ((const float4*)src)[k4];
    }
    float bhr = dec_bhh[jh], bhz = dec_bhh[512 + jh], bhn = dec_bhh[1024 + jh];
    float ba  = A_b[jh];
    int len2 = src_lengths[bx & 31];
    float av[16];
#pragma unroll
    for (int m = 0; m < 16; m++) av[m] = A_v[lane + m * 32];
    int mylen = tgt_lengths[lane];
    const float4* wR = sW1 + (0 + w) * 128;
    const float4* wZ = sW1 + (4 + w) * 128;
    const float4* wN = sW1 + (8 + w) * 128;
    const float4* wA = sW1 + (12 + w) * 128;
    const float* Pr = g_P + ((size_t)lane * G3 + jh) * S;
    const float* Pz = Pr + (size_t)512 * S;
    const float* Pn = Pr + (size_t)1024 * S;
    unsigned bt = 0;

    for (int i = 0; i < T; i++) {
        float ghr, ghz, ghn;
        {
            const float* hin = g_hTd[i & 1];
            __syncthreads();
            for (int idx = tid; idx < 4096; idx += 128)
                sH[idx] = ((const float4*)hin)[idx];
            __syncthreads();
            float aR = bhr, aZ = bhz, aN = bhn, aA = ba;
#pragma unroll 4
            for (int k4 = 0; k4 < 128; k4++) {
                float4 h4 = sH[k4 * B + lane];
                float4 r4 = wR[k4], z4 = wZ[k4], n4 = wN[k4], a4 = wA[k4];
                aR = fmaf(r4.x, h4.x, aR); aR = fmaf(r4.y, h4.y, aR); aR = fmaf(r4.z, h4.z, aR); aR = fmaf(r4.w, h4.w, aR);
                aZ = fmaf(z4.x, h4.x, aZ); aZ = fmaf(z4.y, h4.y, aZ); aZ = fmaf(z4.z, h4.z, aZ); aZ = fmaf(z4.w, h4.w, aZ);
                aN = fmaf(n4.x, h4.x, aN); aN = fmaf(n4.y, h4.y, aN); aN = fmaf(n4.z, h4.z, aN); aN = fmaf(n4.w, h4.w, aN);
                aA = fmaf(a4.x, h4.x, aA); aA = fmaf(a4.y, h4.y, aA); aA = fmaf(a4.z, h4.z, aA); aA = fmaf(a4.w, h4.w, aA);
            }
            ghr = aR; ghz = aZ; ghn = aN;
            g_Ah[lane * H + jh] = aA;
        }
        bar_sync(&g_cnt_dec[0], (++bt) * DEC_BLOCKS);

        if (bx < 32) {
            int b2 = bx;
            float ah[16];
#pragma unroll
            for (int m = 0; m < 16; m++) ah[m] = g_Ah[b2 * H + lane + m * 32];
#pragma unroll
            for (int si = 0; si < 16; si++) {
                int s = w * 16 + si;
                const float* uh = g_Uh + (size_t)(b2 * S + s) * H;
                float p = 0.f;
#pragma unroll
                for (int m = 0; m < 16; m++)
                    p = fmaf(av[m], tanh_fast(uh[lane + m * 32] + ah[m]), p);
#pragma unroll
                for (int off = 16; off; off >>= 1) p += __shfl_xor_sync(0xffffffffu, p, off);
                if (lane == 0) se[s] = (s < len2) ? p : -1e9f;
            }
            __syncthreads();
            if (w == 0) {
                float e0 = se[lane], e1 = se[lane + 32];
                float m = fmaxf(e0, e1);
#pragma unroll
                for (int off = 16; off; off >>= 1) m = fmaxf(m, __shfl_xor_sync(0xffffffffu, m, off));
                float x0 = __expf(e0 - m), x1 = __expf(e1 - m);
                float sm = x0 + x1;
#pragma unroll
                for (int off = 16; off; off >>= 1) sm += __shfl_xor_sync(0xffffffffu, sm, off);
                float inv = 1.0f / sm;
                g_alpha[b2 * S + lane] = x0 * inv;
                g_alpha[b2 * S + lane + 32] = x1 * inv;
            }
        }
        bar_sync(&g_cnt_dec[0], (++bt) * DEC_BLOCKS);

        {
            for (int idx = tid; idx < B * S; idx += 128) {
                int s = idx >> 5, b = idx & 31;
                sAl[s * 33 + b] = g_alpha[b * S + s];
            }
            __syncthreads();
            float ar = 0.f, az = 0.f, an = 0.f;
#pragma unroll 8
            for (int s = 0; s < S; s++) {
                float a = sAl[s * 33 + lane];
                ar = fmaf(a, Pr[s], ar);
                az = fmaf(a, Pz[s], az);
                an = fmaf(a, Pn[s], an);
            }
            const float* gxt = g_gxemb + (size_t)i * G3 * B;
            float gxr = gxt[(size_t)jh * B + lane] + ar;
            float gxz = gxt[(size_t)(512 + jh) * B + lane] + az;
            float gxn = gxt[(size_t)(1024 + jh) * B + lane] + an;
            float r = sigm(gxr + ghr);
            float z = sigm(gxz + ghz);
            float n = tanhf(gxn + r * ghn);
            int hidx = (jh >> 2) * (B * 4) + lane * 4 + (jh & 3);
            float hprev = g_hTd[i & 1][hidx];
            float hnew = (1.f - z) * n + z * hprev;
            int mask = i < mylen;
            g_hTd[(i + 1) & 1][hidx] = mask ? hnew : hprev;
            g_abf[(size_t)(lane * T + i) * H + jh] = __float2bfloat16(mask ? hnew : 0.f);
            __syncthreads();
        }
        if (i < T - 1) bar_sync(&g_cnt_dec[0], (++bt) * DEC_BLOCKS);
    }
}

__global__ __launch_bounds__(256) void cvt_bf16(const float* __restrict__ src,
                                                __nv_bfloat16* __restrict__ dst, int n8)
{
    int i = blockIdx.x * 256 + threadIdx.x;
    if (i < n8) {
        float4 a = ((const float4*)src)[i * 2], b = ((const float4*)src)[i * 2 + 1];
        __nv_bfloat162 o[4];
        o[0] = __nv_bfloat162(__float2bfloat16(a.x), __float2bfloat16(a.y));
        o[1] = __nv_bfloat162(__float2bfloat16(a.z), __float2bfloat16(a.w));
        o[2] = __nv_bfloat162(__float2bfloat16(b.x), __float2bfloat16(b.y));
        o[3] = __nv_bfloat162(__float2bfloat16(b.z), __float2bfloat16(b.w));
        ((uint4*)dst)[i] = *(uint4*)o;
    }
}

// ---------------- bf16 mma logits GEMM (pipelined) + fused per-tile online LSE ----------------
#define LBM 128
#define LBN 128
#define LBK 32
#define LPAD 8
__device__ __forceinline__ void mma16816(float* d, const unsigned* a, const unsigned* b) {
    asm volatile("mma.sync.aligned.m16n8k16.row.col.f32.bf16.bf16.f32 "
        "{%0,%1,%2,%3},{%4,%5,%6,%7},{%8,%9},{%0,%1,%2,%3};"
        : "+f"(d[0]), "+f"(d[1]), "+f"(d[2]), "+f"(d[3])
        : "r"(a[0]), "r"(a[1]), "r"(a[2]), "r"(a[3]), "r"(b[0]), "r"(b[1]));
}
__global__ __launch_bounds__(256) void gemm_logits(const float* __restrict__ out_b)
{
    __shared__ __nv_bfloat16 As[LBM][LBK + LPAD];
    __shared__ __nv_bfloat16 Ws[LBN][LBK + LPAD];
    __shared__ float smM[LBM][4], smS[LBM][4];
    int tid = threadIdx.x;
    int m0 = blockIdx.y * LBM, n0 = blockIdx.x * LBN;
    int wid = tid >> 5, lane = tid & 31;
    int wm = (wid & 1) * 64, wn = (wid >> 1) * 32;
    float acc[4][4][4];
#pragma unroll
    for (int a = 0; a < 4; a++)
#pragma unroll
        for (int b = 0; b < 4; b++)
#pragma unroll
            for (int c = 0; c < 4; c++) acc[a][b][c] = 0.f;

    int lr = tid >> 1, lc = (tid & 1) * 16;
    const __nv_bfloat16* Aptr = g_abf + (size_t)(m0 + lr) * H + lc;
    const __nv_bfloat16* Wptr = g_wbf + (size_t)(n0 + lr) * H + lc;
    uint4 va  = *(const uint4*)(Aptr);
    uint4 va2 = *(const uint4*)(Aptr + 8);
    uint4 vw  = *(const uint4*)(Wptr);
    uint4 vw2 = *(const uint4*)(Wptr + 8);

    for (int k0 = 0; k0 < H; k0 += LBK) {
        __syncthreads();
        *(uint4*)&As[lr][lc] = va;  *(uint4*)&As[lr][lc + 8] = va2;
        *(uint4*)&Ws[lr][lc] = vw;  *(uint4*)&Ws[lr][lc + 8] = vw2;
        __syncthreads();
        if (k0 + LBK < H) {
            va  = *(const uint4*)(Aptr + k0 + LBK);
            va2 = *(const uint4*)(Aptr + k0 + LBK + 8);
            vw  = *(const uint4*)(Wptr + k0 + LBK);
            vw2 = *(const uint4*)(Wptr + k0 + LBK + 8);
        }
#pragma unroll
        for (int kk = 0; kk < LBK; kk += 16) {
            unsigned af[4][4], bfr[4][2];
            int arow = lane >> 2, acol = kk + (lane & 3) * 2;
#pragma unroll
            for (int mf = 0; mf < 4; mf++) {
                af[mf][0] = *(const unsigned*)&As[wm + mf * 16 + arow][acol];
                af[mf][1] = *(const unsigned*)&As[wm + mf * 16 + arow + 8][acol];
                af[mf][2] = *(const unsigned*)&As[wm + mf * 16 + arow][acol + 8];
                af[mf][3] = *(const unsigned*)&As[wm + mf * 16 + arow + 8][acol + 8];
            }
#pragma unroll
            for (int nf = 0; nf < 4; nf++) {
                int brow = wn + nf * 8 + (lane >> 2);
                bfr[nf][0] = *(const unsigned*)&Ws[brow][acol];
                bfr[nf][1] = *(const unsigned*)&Ws[brow][acol + 8];
            }
#pragma unroll
            for (int mf = 0; mf < 4; mf++)
#pragma unroll
                for (int nf = 0; nf < 4; nf++) mma16816(acc[mf][nf], af[mf], bfr[nf]);
        }
    }
    float bb[4][2];
#pragma unroll
    for (int nf = 0; nf < 4; nf++) {
        int n = n0 + wn + nf * 8 + (lane & 3) * 2;
        bb[nf][0] = out_b[n]; bb[nf][1] = out_b[n + 1];
    }
    __syncthreads();
#pragma unroll
    for (int half = 0; half < 2; half++) {
#pragma unroll
        for (int mf = 0; mf < 4; mf++) {
            float m = -1e30f, s = 0.f;
#pragma unroll
            for (int nf = 0; nf < 4; nf++) {
#pragma unroll
                for (int c = 0; c < 2; c++) {
                    float x = acc[mf][nf][half * 2 + c] + bb[nf][c];
                    if (x > m) { s = s * __expf(m - x) + 1.f; m = x; }
                    else s += __expf(x - m);
                }
            }
#pragma unroll
            for (int off = 1; off < 4; off <<= 1) {
                float m2 = __shfl_xor_sync(0xffffffffu, m, off);
                float s2 = __shfl_xor_sync(0xffffffffu, s, off);
                float mm = fmaxf(m, m2);
                s = s * __expf(m - mm) + s2 * __expf(m2 - mm);
                m = mm;
            }
            if ((lane & 3) == 0) {
                int rr = wm + mf * 16 + (lane >> 2) + 8 * half;
                smM[rr][wid >> 1] = m; smS[rr][wid >> 1] = s;
            }
        }
    }
    __syncthreads();
    if (tid < LBM) {
        float m = smM[tid][0], s = smS[tid][0];
#pragma unroll
        for (int q = 1; q < 4; q++) {
            float m2 = smM[tid][q], s2 = smS[tid][q];
            float mm = fmaxf(m, m2);
            s = s * __expf(m - mm) + s2 * __expf(m2 - mm);
            m = mm;
        }
        g_pm[(size_t)(m0 + tid) * NB + blockIdx.x] = m;
        g_ps[(size_t)(m0 + tid) * NB + blockIdx.x] = s;
    }
}

// ---------------- merge partials + picked logit ----------------
__global__ __launch_bounds__(256) void merge_lse(
    const int* __restrict__ tgt_seqs, const float* __restrict__ out_b)
{
    int row = blockIdx.x, b = row / T, t = row % T;
    int tid = threadIdx.x;
    int goal = (t < T - 1) ? tgt_seqs[b * T + t + 1] : 0;
    __shared__ float sm_[256], ss_[256];
    float m = -1e30f, s = 0.f;
    if (tid < NB) { m = g_pm[(size_t)row * NB + tid]; s = g_ps[(size_t)row * NB + tid]; }
    sm_[tid] = m; ss_[tid] = s; __syncthreads();
    for (int q = 128; q; q >>= 1) {
        if (tid < q) {
            float m1 = sm_[tid], s1 = ss_[tid], m2 = sm_[tid + q], s2 = ss_[tid + q];
            float mm = fmaxf(m1, m2);
            sm_[tid] = mm; ss_[tid] = s1 * __expf(m1 - mm) + s2 * __expf(m2 - mm);
        }
        __syncthreads();
    }
    float lse = sm_[0] + logf(ss_[0]);
    float p = 0.f;
    if (goal != 0) {
        for (int k = tid; k < H; k += 256)
            p += __bfloat162float(g_abf[(size_t)row * H + k]) *
                 __bfloat162float(g_wbf[(size_t)goal * H + k]);
    }
    __syncthreads();
    sm_[tid] = p; __syncthreads();
    for (int q = 128; q; q >>= 1) {
        if (tid < q) sm_[tid] += sm_[tid + q];
        __syncthreads();
    }
    if (tid == 0)
        g_rowres[row] = (goal != 0) ? (sm_[0] + out_b[goal] - lse) : 0.f;
}

__global__ __launch_bounds__(256) void final_loss(
    const int* __restrict__ tgt_seqs, float* __restrict__ out)
{
    __shared__ float sp[256], sc[256];
    int tid = threadIdx.x;
    float ps = 0.f, pc = 0.f;
    for (int r = tid; r < B * T; r += 256) {
        ps += g_rowres[r];
        int b = r / T, t = r % T;
        int goal = (t < T - 1) ? tgt_seqs[b * T + t + 1] : 0;
        pc += (goal != 0) ? 1.f : 0.f;
    }
    sp[tid] = ps; sc[tid] = pc; __syncthreads();
    for (int q = 128; q; q >>= 1) {
        if (tid < q) { sp[tid] += sp[tid + q]; sc[tid] += sc[tid + q]; }
        __syncthreads();
    }
    if (tid == 0) out[0] = -sp[0] / sc[0];
}

extern "C" void kernel_launch(void* const* d_in, const int* in_sizes, int n_in,
                              void* d_out, int out_size)
{
    const int* src_seqs    = (const int*)d_in[0];
    const int* src_lengths = (const int*)d_in[1];
    const int* tgt_seqs    = (const int*)d_in[2];
    const int* tgt_lengths = (const int*)d_in[3];
    const float* src_emb   = (const float*)d_in[4];
    const float* enc_Wih_f = (const float*)d_in[5];
    const float* enc_Whh_f = (const float*)d_in[6];
    const float* enc_bih_f = (const float*)d_in[7];
    const float* enc_bhh_f = (const float*)d_in[8];
    const float* enc_Wih_b = (const float*)d_in[9];
    const float* enc_Whh_b = (const float*)d_in[10];
    const float* enc_bih_b = (const float*)d_in[11];
    const float* enc_bhh_b = (const float*)d_in[12];
    const float* tgt_emb   = (const float*)d_in[13];
    const float* dec_Wih   = (const float*)d_in[14];
    const float* dec_Whh   = (const float*)d_in[15];
    const float* dec_bih   = (const float*)d_in[16];
    const float* dec_bhh   = (const float*)d_in[17];
    const float* U_w       = (const float*)d_in[18];
    const float* U_b       = (const float*)d_in[19];
    const float* A_W       = (const float*)d_in[20];
    const float* A_b       = (const float*)d_in[21];
    const float* A_v       = (const float*)d_in[22];
    const float* out_w     = (const float*)d_in[23];
    const float* out_b     = (const float*)d_in[24];

    void *p_esrc, *p_etgt, *p_gxf, *p_gxb, *p_gxemb, *p_srchid, *p_Uh, *p_P, *p_wbf, *p_zb;
    cudaGetSymbolAddress(&p_esrc, g_esrc);
    cudaGetSymbolAddress(&p_etgt, g_etgt);
    cudaGetSymbolAddress(&p_gxf, g_gxf);
    cudaGetSymbolAddress(&p_gxb, g_gxb);
    cudaGetSymbolAddress(&p_gxemb, g_gxemb);
    cudaGetSymbolAddress(&p_srchid, g_srchid);
    cudaGetSymbolAddress(&p_Uh, g_Uh);
    cudaGetSymbolAddress(&p_P, g_P);
    cudaGetSymbolAddress(&p_wbf, g_wbf);
    cudaGetSymbolAddress(&p_zb, g_zb);

    const int enc_smem = (3072 + 4096) * 16;
    const int dec_smem = (2048 + 4096) * 16;
    cudaFuncSetAttribute(enc_persist, cudaFuncAttributeMaxDynamicSharedMemorySize, enc_smem);
    cudaFuncSetAttribute(dec_persist, cudaFuncAttributeMaxDynamicSharedMemorySize, dec_smem);

    // Launch order arranged so ncu's capture slot (-s 5 -c 1) lands on enc_persist.
    zero_h_kernel<<<(H * B + 255) / 256, 256>>>();                                  // 0
    embed_kernel<<<B * S + B * T, 128>>>(src_seqs, tgt_seqs, src_emb, tgt_emb);     // 1

    gemm_nt<1><<<dim3(G3 / GBN, (B * S) / GBM), 256>>>(
        (const float*)p_esrc, E, enc_Wih_f, E, enc_bih_f, (float*)p_gxf, G3, E, S); // 2
    gemm_nt<1><<<dim3(G3 / GBN, (B * S) / GBM), 256>>>(
        (const float*)p_esrc, E, enc_Wih_b, E, enc_bih_b, (float*)p_gxb, G3, E, S); // 3
    gemm_nt<1><<<dim3(G3 / GBN, (B * T) / GBM), 256>>>(
        (const float*)p_etgt, E, dec_Wih, G3, dec_bih, (float*)p_gxemb, G3, E, T);  // 4

    enc_persist<<<ENC_BLOCKS, 256, enc_smem>>>(enc_Whh_f, enc_bhh_f,
                                               enc_Whh_b, enc_bhh_b, src_lengths); // 5 <- profiled

    gemm_nt<0><<<dim3(H / GBN, (B * S) / GBM), 256>>>(
        (const float*)p_srchid, 2 * H, U_w, 2 * H, U_b, (float*)p_Uh, H, 2 * H, S);
    gemm_nt<2><<<dim3(G3 / GBN, (B * S) / GBM), 256>>>(
        (const float*)p_srchid, 2 * H, dec_Wih + 512, G3, (const float*)p_zb, (float*)p_P, 0, 2 * H, S);

    cvt_bf16<<<((int)((size_t)V * H / 8) + 255) / 256, 256>>>(out_w,
                                                   (__nv_bfloat16*)p_wbf, (int)((size_t)V * H / 8));

    dec_persist<<<DEC_BLOCKS, 128, dec_smem>>>(dec_Whh, dec_bhh, A_W, A_b, A_v,
                                               src_lengths, tgt_lengths);

    gemm_logits<<<dim3(V / LBN, (B * T) / LBM), 256>>>(out_b);
    merge_lse<<<B * T, 256>>>(tgt_seqs, out_b);
    final_loss<<<1, 256>>>(tgt_seqs, (float*)d_out);
}